// round 8
// baseline (speedup 1.0000x reference)
#include <cuda_runtime.h>
#include <cuda.h>
#include <cuda_bf16.h>
#include <cstdint>

#define NTOK   8192
#define DIM    1024
#define NEXP   8
#define CAP    1024
#define LN_EPS 1e-5f

// Arch-specific feature gate: tcgen05 only exists on sm_100a/sm_103a targets.
#if defined(__CUDA_ARCH_FEAT_SM103_ALL) || defined(__CUDA_ARCH_FEAT_SM100_ALL)
#define HAS_TCGEN05 1
#else
#define HAS_TCGEN05 0
#endif

// ---------------- scratch (device globals: no allocation) -------------------
__device__ __nv_bfloat16 g_xhi[NTOK * DIM];
__device__ __nv_bfloat16 g_xlo[NTOK * DIM];
__device__ __nv_bfloat16 g_whi[NEXP * DIM * DIM];   // transposed: [e][n][k]
__device__ __nv_bfloat16 g_wlo[NEXP * DIM * DIM];
__device__ float         g_h  [NTOK * DIM];

// ---------------- PTX helpers (guarded) -------------------------------------
#if HAS_TCGEN05
__device__ __forceinline__ uint32_t smem_u32(const void* p) {
    uint32_t a;
    asm("{ .reg .u64 t; cvta.to.shared.u64 t, %1; cvt.u32.u64 %0, t; }" : "=r"(a) : "l"(p));
    return a;
}
__device__ __forceinline__ uint32_t elect_one_pred() {
    uint32_t p;
    asm volatile("{\n\t.reg .pred p;\n\telect.sync _|p, 0xFFFFFFFF;\n\tselp.b32 %0, 1, 0, p;\n\t}" : "=r"(p));
    return p;
}

#define MBARRIER_INIT(addr, cnt) \
    asm volatile("mbarrier.init.shared.b64 [%0], %1;" :: "r"(addr), "r"(cnt) : "memory")
#define MBARRIER_INVAL(addr) \
    asm volatile("mbarrier.inval.shared.b64 [%0];" :: "r"(addr) : "memory")
#define MBARRIER_EXPECT_TX(addr, bytes) \
    asm volatile("mbarrier.arrive.expect_tx.shared.b64 _, [%0], %1;" :: "r"(addr), "r"(bytes) : "memory")
#define MBARRIER_WAIT_PARITY(addr, par) do {                                        \
    uint32_t _m = (addr), _p = (par), _d;                                           \
    asm volatile("{\n\t.reg .pred p;\n\t"                                           \
        "mbarrier.try_wait.parity.acquire.cta.shared::cta.b64 p, [%1], %2;\n\t"     \
        "selp.b32 %0, 1, 0, p;\n\t}" : "=r"(_d) : "r"(_m), "r"(_p) : "memory");     \
    if (!_d) {                                                                      \
        asm volatile("{\n\t.reg .pred P1;\n\t"                                      \
            "WL_%=:\n\t"                                                            \
            "mbarrier.try_wait.parity.acquire.cta.shared::cta.b64 P1, [%0], %1, 0x989680;\n\t" \
            "@P1 bra.uni WD_%=;\n\tbra.uni WL_%=;\n\tWD_%=:\n\t}"                   \
            :: "r"(_m), "r"(_p) : "memory");                                        \
    } } while (0)

#define TMA_LOAD_2D_MC(smem_addr, map, cx, cy, mbar, mask) \
    asm volatile("cp.async.bulk.tensor.2d.shared::cluster.global.tile.mbarrier::complete_tx::bytes.multicast::cluster " \
        "[%0], [%1, {%2, %3}], [%4], %5;" \
        :: "r"(smem_addr), "l"(map), "r"(cx), "r"(cy), "r"(mbar), "h"((uint16_t)(mask)) : "memory")

#define CLUSTER_SYNC() do { \
    asm volatile("barrier.cluster.arrive.aligned;" ::: "memory"); \
    asm volatile("barrier.cluster.wait.aligned;"   ::: "memory"); } while (0)

#define TCGEN05_ALLOC(smem_addr, ncols) \
    asm volatile("tcgen05.alloc.cta_group::1.sync.aligned.shared::cta.b32 [%0], %1;" \
                 :: "r"(smem_addr), "r"(ncols) : "memory")
#define TCGEN05_DEALLOC(tmem, ncols) \
    asm volatile("tcgen05.dealloc.cta_group::1.sync.aligned.b32 %0, %1;" :: "r"(tmem), "r"(ncols))
#define TCGEN05_RELINQ() \
    asm volatile("tcgen05.relinquish_alloc_permit.cta_group::1.sync.aligned;")
#define TCGEN05_COMMIT(mbar) \
    asm volatile("tcgen05.commit.cta_group::1.mbarrier::arrive::one.shared::cluster.b64 [%0];" \
                 :: "r"(mbar) : "memory")
#define TCGEN05_COMMIT_MC(mbar, mask) \
    asm volatile("tcgen05.commit.cta_group::1.mbarrier::arrive::one.shared::cluster.multicast::cluster.b64 [%0], %1;" \
                 :: "r"(mbar), "h"((uint16_t)(mask)) : "memory")
#define TCGEN05_FENCE_AFTER() \
    asm volatile("tcgen05.fence::after_thread_sync;" ::: "memory")
#define TCGEN05_FENCE_BEFORE() \
    asm volatile("tcgen05.fence::before_thread_sync;" ::: "memory")
#define TCGEN05_WAIT_LD() \
    asm volatile("tcgen05.wait::ld.sync.aligned;" ::: "memory")

#define TCGEN05_LD_X32(r, tmem_addr) \
    asm volatile("tcgen05.ld.sync.aligned.32x32b.x32.b32 " \
        "{%0, %1, %2, %3, %4, %5, %6, %7, %8, %9, %10, %11, %12, %13, %14, %15, " \
        " %16, %17, %18, %19, %20, %21, %22, %23, %24, %25, %26, %27, %28, %29, %30, %31}, [%32];" \
        : "=r"((r)[0]),  "=r"((r)[1]),  "=r"((r)[2]),  "=r"((r)[3]),  \
          "=r"((r)[4]),  "=r"((r)[5]),  "=r"((r)[6]),  "=r"((r)[7]),  \
          "=r"((r)[8]),  "=r"((r)[9]),  "=r"((r)[10]), "=r"((r)[11]), \
          "=r"((r)[12]), "=r"((r)[13]), "=r"((r)[14]), "=r"((r)[15]), \
          "=r"((r)[16]), "=r"((r)[17]), "=r"((r)[18]), "=r"((r)[19]), \
          "=r"((r)[20]), "=r"((r)[21]), "=r"((r)[22]), "=r"((r)[23]), \
          "=r"((r)[24]), "=r"((r)[25]), "=r"((r)[26]), "=r"((r)[27]), \
          "=r"((r)[28]), "=r"((r)[29]), "=r"((r)[30]), "=r"((r)[31]) \
        : "r"(tmem_addr))

// SS-mode bf16 MMA, cta_group::1, fp32 accumulate in TMEM
__device__ __forceinline__ void mma_f16_ss(uint32_t d_tmem, uint64_t a_desc,
                                           uint64_t b_desc, uint32_t idesc, bool acc) {
    uint32_t en = acc ? 1u : 0u, z = 0u;
    asm volatile("{\n\t.reg .pred p;\n\tsetp.ne.u32 p, %5, 0;\n\t"
        "tcgen05.mma.cta_group::1.kind::f16 [%0], %1, %2, %3, {%4, %4, %4, %4}, p;\n\t}"
        :: "r"(d_tmem), "l"(a_desc), "l"(b_desc), "r"(idesc), "r"(z), "r"(en) : "memory");
}

// SW64 K-major descriptor: layout=4 (SW64), version=1, SBO=32 (512B = 8 rows x 64B), LBO=1
static __device__ __forceinline__ uint64_t make_desc_sw64(uint32_t addr) {
    const uint64_t BASE = (4ull << 61) | (1ull << 46) | (32ull << 32) | (1ull << 16);
    return BASE | ((uint64_t)(addr >> 4) & 0x3FFFull);
}

// idesc: F32 out, BF16 in, M=128, N=256
#define MMA_IDESC ((1u << 4) | (1u << 7) | (1u << 10) | ((256u / 8) << 17) | ((128u / 16) << 24))
#endif // HAS_TCGEN05

// ---------------------------------------------------------------------------
// Conversion: X fp32 -> (hi, lo) bf16
// ---------------------------------------------------------------------------
__global__ __launch_bounds__(256)
void convert_x_kernel(const float* __restrict__ X,
                      __nv_bfloat16* __restrict__ Xhi,
                      __nv_bfloat16* __restrict__ Xlo)
{
    int idx = blockIdx.x * 256 + threadIdx.x;       // float4 index
    float4 v = ((const float4*)X)[idx];
    __nv_bfloat16 h[4], l[4];
    float vv[4] = {v.x, v.y, v.z, v.w};
    #pragma unroll
    for (int i = 0; i < 4; ++i) {
        h[i] = __float2bfloat16(vv[i]);
        l[i] = __float2bfloat16(vv[i] - __bfloat162float(h[i]));
    }
    *(uint2*)(Xhi + (size_t)idx * 4) = *(uint2*)h;
    *(uint2*)(Xlo + (size_t)idx * 4) = *(uint2*)l;
}

// ---------------------------------------------------------------------------
// Conversion + transpose: W[e][k][n] fp32 -> Wt(hi/lo)[e][n][k] bf16
// ---------------------------------------------------------------------------
__global__ __launch_bounds__(256)
void convert_w_kernel(const float* __restrict__ W,
                      __nv_bfloat16* __restrict__ Whi,
                      __nv_bfloat16* __restrict__ Wlo)
{
    __shared__ float t[32][33];
    const int e  = blockIdx.z;
    const int k0 = blockIdx.y * 32;
    const int n0 = blockIdx.x * 32;
    const int tx = threadIdx.x & 31;
    const int ty = threadIdx.x >> 5;    // 0..7

    const float* Wp = W + (size_t)e * DIM * DIM;
    #pragma unroll
    for (int r = 0; r < 4; ++r) {
        int k = k0 + ty + 8 * r;
        t[ty + 8 * r][tx] = Wp[(size_t)k * DIM + n0 + tx];
    }
    __syncthreads();
    #pragma unroll
    for (int r = 0; r < 4; ++r) {
        int n = n0 + ty + 8 * r;
        float v = t[tx][ty + 8 * r];
        __nv_bfloat16 h = __float2bfloat16(v);
        __nv_bfloat16 l = __float2bfloat16(v - __bfloat162float(h));
        size_t off = (size_t)e * DIM * DIM + (size_t)n * DIM + k0 + tx;
        Whi[off] = h;
        Wlo[off] = l;
    }
}

// ---------------------------------------------------------------------------
// GEMM: per expert e, H = relu(X_e @ W_e + b_e), bf16x3 split.
//   sm_103a: TMA-multicast over (2,2) cluster, tile M=256 N=256, 3 stages.
//   Each CTA TMA-loads half of A (rx) and half of B (ry), multicasting to the
//   partner that shares that operand. empty[] barriers released cluster-wide
//   via tcgen05.commit multicast (count=4).
// ---------------------------------------------------------------------------
#define NSTAGE      3
#define K_CHUNK     32
#define N_CHUNKS    32               // 1024 / 32
#define STAGE_BYTES 65536            // Ahi16K Alo16K Bhi16K Blo16K (256 rows x 64B each)
#define OFF_BIAS  (NSTAGE * STAGE_BYTES)       // 196608, 1KB
#define OFF_TPTR  (OFF_BIAS + 1024)
#define OFF_FULL  (OFF_TPTR + 16)              // 3 x 8B
#define OFF_EMPTY (OFF_FULL + 24)              // 3 x 8B
#define OFF_FINAL (OFF_EMPTY + 24)
#define SMEM_SIZE (OFF_FINAL + 8)

__global__ __launch_bounds__(256, 1) __cluster_dims__(2, 2, 1)
void gemm_tc_kernel(const __grid_constant__ CUtensorMap tmXhi,
                    const __grid_constant__ CUtensorMap tmXlo,
                    const __grid_constant__ CUtensorMap tmWhi,
                    const __grid_constant__ CUtensorMap tmWlo,
                    const __nv_bfloat16* __restrict__ Xhi,
                    const __nv_bfloat16* __restrict__ Xlo,
                    const __nv_bfloat16* __restrict__ Whi,
                    const __nv_bfloat16* __restrict__ Wlo,
                    const float* __restrict__ bias,
                    float* __restrict__ H)
{
#if HAS_TCGEN05
    extern __shared__ __align__(1024) char smem[];
    const uint32_t sbase  = smem_u32(smem);
    const int e      = blockIdx.z;
    const int tile_n = blockIdx.x * 256;
    const int tile_m = blockIdx.y * 256;
    const int rx     = blockIdx.x & 1;          // rank = rx + 2*ry (x-fastest)
    const int ry     = blockIdx.y & 1;
    const uint16_t maskA = (uint16_t)(0x3u << (2 * ry));   // partners sharing A
    const uint16_t maskB = (uint16_t)(0x5u << rx);         // partners sharing B
    const int tid    = threadIdx.x;
    const int wid    = tid >> 5;
    const int lid    = tid & 31;

    if (wid == 0) {
        TCGEN05_ALLOC(sbase + OFF_TPTR, 512);
        TCGEN05_RELINQ();
    }
    if (tid == 0) {
        #pragma unroll
        for (int s = 0; s < NSTAGE; ++s) {
            MBARRIER_INIT(sbase + OFF_FULL  + s * 8, 1);   // expect_tx arrive by tid0
            MBARRIER_INIT(sbase + OFF_EMPTY + s * 8, 4);   // commit-MC from all 4 CTAs
        }
        MBARRIER_INIT(sbase + OFF_FINAL, 1);
    }
    ((float*)(smem + OFF_BIAS))[tid] = bias[e * DIM + tile_n + tid];
    __syncthreads();
    CLUSTER_SYNC();                 // all cluster mbarriers live before any MC TMA
    uint32_t tmem;
    asm volatile("ld.shared.b32 %0, [%1];" : "=r"(tmem) : "r"(sbase + OFF_TPTR));

    if (tid == 0) {
        // ------- producer: 4 multicast TMA issues per chunk (half A + half B)
        const int rowA = e * CAP + tile_m + rx * 128;      // X rows (this CTA's half)
        const int rowB = e * DIM + tile_n + ry * 128;      // Wt rows (this CTA's half)
        int st = 0, it = 0;
        for (int c = 0; c < N_CHUNKS; ++c) {
            if (c >= NSTAGE)
                MBARRIER_WAIT_PARITY(sbase + OFF_EMPTY + st * 8, (it - 1) & 1);
            const uint32_t bb = sbase + st * STAGE_BYTES;
            const uint32_t fb = sbase + OFF_FULL + st * 8;
            const int cx = c * K_CHUNK;
            MBARRIER_EXPECT_TX(fb, STAGE_BYTES);           // full tile: 4 x 16KB
            TMA_LOAD_2D_MC(bb + 0     + rx * 8192, &tmXhi, cx, rowA, fb, maskA);
            TMA_LOAD_2D_MC(bb + 16384 + rx * 8192, &tmXlo, cx, rowA, fb, maskA);
            TMA_LOAD_2D_MC(bb + 32768 + ry * 8192, &tmWhi, cx, rowB, fb, maskB);
            TMA_LOAD_2D_MC(bb + 49152 + ry * 8192, &tmWlo, cx, rowB, fb, maskB);
            if (++st == NSTAGE) { st = 0; ++it; }
        }
    } else if (wid == 1) {
        // ---------------- MMA warp (single elected thread)
        if (elect_one_pred()) {
            int st = 0, it = 0;
            for (int c = 0; c < N_CHUNKS; ++c) {
                MBARRIER_WAIT_PARITY(sbase + OFF_FULL + st * 8, it & 1);
                const uint32_t bb = sbase + st * STAGE_BYTES;
                uint64_t dAh = make_desc_sw64(bb + 0);
                uint64_t dAl = make_desc_sw64(bb + 16384);
                uint64_t dBh = make_desc_sw64(bb + 32768);
                uint64_t dBl = make_desc_sw64(bb + 49152);
                #pragma unroll
                for (int h = 0; h < 2; ++h) {
                    const uint32_t D   = tmem + h * 256;
                    const uint64_t hof = h * 512;             // 128 rows x 64B = 512 units
                    #pragma unroll
                    for (int kk = 0; kk < 2; ++kk) {
                        mma_f16_ss(D, dAh + hof + kk * 2, dBh + kk * 2, MMA_IDESC,
                                   !(c == 0 && kk == 0));
                        mma_f16_ss(D, dAh + hof + kk * 2, dBl + kk * 2, MMA_IDESC, true);
                        mma_f16_ss(D, dAl + hof + kk * 2, dBh + kk * 2, MMA_IDESC, true);
                    }
                }
                TCGEN05_COMMIT_MC(sbase + OFF_EMPTY + st * 8, 0xF);
                if (++st == NSTAGE) { st = 0; ++it; }
            }
            TCGEN05_COMMIT(sbase + OFF_FINAL);
        }
    }

    // ---------------- epilogue: all 8 warps after this CTA's MMAs complete
    MBARRIER_WAIT_PARITY(sbase + OFF_FINAL, 0);
    TCGEN05_FENCE_AFTER();

    {
        const int half = wid >> 2, sub = wid & 3;
        const int row  = tile_m + half * 128 + sub * 32 + lid;
        float* outp = H + (size_t)(e * CAP + row) * DIM + tile_n;
        const float* bs = (const float*)(smem + OFF_BIAS);
        const uint32_t dbase = tmem + half * 256;
        #pragma unroll
        for (int base = 0; base < 256; base += 32) {
            uint32_t r[32];
            TCGEN05_LD_X32(r, dbase + base);
            TCGEN05_WAIT_LD();
            float v[32];
            #pragma unroll
            for (int i = 0; i < 32; ++i)
                v[i] = fmaxf(__uint_as_float(r[i]) + bs[base + i], 0.f);
            #pragma unroll
            for (int q = 0; q < 8; ++q)
                *(float4*)(outp + base + q * 4) = *(float4*)&v[q * 4];
        }
        TCGEN05_FENCE_BEFORE();
    }
    __syncthreads();
    if (tid == 0) {
        #pragma unroll
        for (int s = 0; s < NSTAGE; ++s) {
            MBARRIER_INVAL(sbase + OFF_FULL  + s * 8);
            MBARRIER_INVAL(sbase + OFF_EMPTY + s * 8);
        }
        MBARRIER_INVAL(sbase + OFF_FINAL);
    }
    __syncthreads();
    if (wid == 0) TCGEN05_DEALLOC(tmem, 512);
    CLUSTER_SYNC();                 // no CTA exits while peer multicasts may target it

#else
    // ---------------- trivial correct fallback (family-level image; not used on GB300)
    const int e      = blockIdx.z;
    const int tile_n = blockIdx.x * 256;
    const int tile_m = blockIdx.y * 256;
    const int tid    = threadIdx.x;
    const int row    = tile_m + tid;
    const __nv_bfloat16* Ahp = Xhi + (size_t)(e * CAP + row) * DIM;
    const __nv_bfloat16* Alp = Xlo + (size_t)(e * CAP + row) * DIM;
    for (int n = 0; n < 256; ++n) {
        const __nv_bfloat16* Bhp = Whi + ((size_t)e * DIM + tile_n + n) * DIM;
        const __nv_bfloat16* Blp = Wlo + ((size_t)e * DIM + tile_n + n) * DIM;
        float s = 0.f;
        for (int k = 0; k < DIM; ++k) {
            float a = __bfloat162float(Ahp[k]) + __bfloat162float(Alp[k]);
            float b = __bfloat162float(Bhp[k]) + __bfloat162float(Blp[k]);
            s = fmaf(a, b, s);
        }
        s += bias[e * DIM + tile_n + n];
        H[(size_t)(e * CAP + row) * DIM + tile_n + n] = fmaxf(s, 0.f);
    }
#endif
}

// ---------------------------------------------------------------------------
// LayerNorm over D=1024 per row; one 256-thread CTA per token. (R3 version)
// ---------------------------------------------------------------------------
__global__ __launch_bounds__(256)
void layernorm_kernel(const float* __restrict__ H,
                      const float* __restrict__ gamma,
                      const float* __restrict__ beta,
                      float* __restrict__ out)
{
    const int row = blockIdx.x;
    const int e   = row >> 10;
    const int tid = threadIdx.x;

    const float* h = H + (size_t)row * DIM;
    float4 v = *(const float4*)(h + tid * 4);

    float s  = v.x + v.y + v.z + v.w;
    float sq = v.x * v.x + v.y * v.y + v.z * v.z + v.w * v.w;

    #pragma unroll
    for (int off = 16; off > 0; off >>= 1) {
        s  += __shfl_xor_sync(0xffffffffu, s,  off);
        sq += __shfl_xor_sync(0xffffffffu, sq, off);
    }

    __shared__ float red_s[8], red_q[8];
    const int wid = tid >> 5, lid = tid & 31;
    if (lid == 0) { red_s[wid] = s; red_q[wid] = sq; }
    __syncthreads();

    __shared__ float s_mean, s_rstd;
    if (wid == 0) {
        float ts = (lid < 8) ? red_s[lid] : 0.f;
        float tq = (lid < 8) ? red_q[lid] : 0.f;
        #pragma unroll
        for (int off = 4; off > 0; off >>= 1) {
            ts += __shfl_xor_sync(0xffffffffu, ts, off);
            tq += __shfl_xor_sync(0xffffffffu, tq, off);
        }
        if (lid == 0) {
            float mean = ts * (1.f / DIM);
            float var  = tq * (1.f / DIM) - mean * mean;
            s_mean = mean;
            s_rstd = rsqrtf(var + LN_EPS);
        }
    }
    __syncthreads();

    const float mean = s_mean, rstd = s_rstd;
    float4 g  = *(const float4*)(gamma + (size_t)e * DIM + tid * 4);
    float4 bt = *(const float4*)(beta  + (size_t)e * DIM + tid * 4);

    float4 o;
    o.x = (v.x - mean) * rstd * g.x + bt.x;
    o.y = (v.y - mean) * rstd * g.y + bt.y;
    o.z = (v.z - mean) * rstd * g.z + bt.z;
    o.w = (v.w - mean) * rstd * g.w + bt.w;
    *(float4*)(out + (size_t)row * DIM + tid * 4) = o;
}

// ---------------------------------------------------------------------------
typedef CUresult (CUDAAPI *pfn_encode_t)(
    CUtensorMap*, CUtensorMapDataType, cuuint32_t, void*,
    const cuuint64_t*, const cuuint64_t*, const cuuint32_t*, const cuuint32_t*,
    CUtensorMapInterleave, CUtensorMapSwizzle, CUtensorMapL2promotion,
    CUtensorMapFloatOOBfill);

static void encode_map_2d(pfn_encode_t fn, CUtensorMap* tm, void* ptr, int nrows)
{
    cuuint64_t dims[2]    = {(cuuint64_t)DIM, (cuuint64_t)nrows};
    cuuint64_t strides[1] = {(cuuint64_t)(DIM * 2)};   // bytes per row (bf16)
    cuuint32_t box[2]     = {32, 128};                 // 64B x 128 rows, SW64
    cuuint32_t estr[2]    = {1, 1};
    fn(tm, CU_TENSOR_MAP_DATA_TYPE_BFLOAT16, 2, ptr, dims, strides, box, estr,
       CU_TENSOR_MAP_INTERLEAVE_NONE, CU_TENSOR_MAP_SWIZZLE_64B,
       CU_TENSOR_MAP_L2_PROMOTION_L2_128B, CU_TENSOR_MAP_FLOAT_OOB_FILL_NONE);
}

extern "C" void kernel_launch(void* const* d_in, const int* in_sizes, int n_in,
                              void* d_out, int out_size)
{
    const float* x     = (const float*)d_in[0];
    // d_in[1] = expert_frequency (equal capacities) — unused
    const float* W     = (const float*)d_in[2];
    const float* bias  = (const float*)d_in[3];
    const float* gamma = (const float*)d_in[4];
    const float* beta  = (const float*)d_in[5];
    float*       out   = (float*)d_out;

    __nv_bfloat16 *xhi, *xlo, *whi, *wlo;
    float* h;
    cudaGetSymbolAddress((void**)&xhi, g_xhi);
    cudaGetSymbolAddress((void**)&xlo, g_xlo);
    cudaGetSymbolAddress((void**)&whi, g_whi);
    cudaGetSymbolAddress((void**)&wlo, g_wlo);
    cudaGetSymbolAddress((void**)&h,   g_h);

    static bool init_done = false;
    static CUtensorMap tmXhi, tmXlo, tmWhi, tmWlo;
    if (!init_done) {
        cudaFuncSetAttribute(gemm_tc_kernel,
                             cudaFuncAttributeMaxDynamicSharedMemorySize, SMEM_SIZE);
        void* p = nullptr;
        cudaDriverEntryPointQueryResult qr;
        if (cudaGetDriverEntryPointByVersion("cuTensorMapEncodeTiled", &p, 12000,
                                             cudaEnableDefault, &qr) != cudaSuccess || !p) {
            cudaGetDriverEntryPoint("cuTensorMapEncodeTiled", &p, cudaEnableDefault, &qr);
        }
        pfn_encode_t fn = (pfn_encode_t)p;
        encode_map_2d(fn, &tmXhi, xhi, NTOK);
        encode_map_2d(fn, &tmXlo, xlo, NTOK);
        encode_map_2d(fn, &tmWhi, whi, NEXP * DIM);
        encode_map_2d(fn, &tmWlo, wlo, NEXP * DIM);
        init_done = true;
    }

    convert_x_kernel<<<NTOK * DIM / (256 * 4), 256>>>(x, xhi, xlo);
    convert_w_kernel<<<dim3(DIM / 32, DIM / 32, NEXP), 256>>>(W, whi, wlo);

    dim3 grid(DIM / 256, CAP / 256, NEXP);  // 4 x 4 x 8 = 128 CTAs, (2,2) clusters
    gemm_tc_kernel<<<grid, 256, SMEM_SIZE>>>(tmXhi, tmXlo, tmWhi, tmWlo,
                                             xhi, xlo, whi, wlo, bias, h);

    layernorm_kernel<<<NTOK, 256>>>(h, gamma, beta, out);
}

// round 9
// speedup vs baseline: 1.0245x; 1.0245x over previous
#include <cuda_runtime.h>
#include <cuda.h>
#include <cuda_bf16.h>
#include <cstdint>

#define NTOK   8192
#define DIM    1024
#define NEXP   8
#define CAP    1024
#define LN_EPS 1e-5f

// Arch-specific feature gate: tcgen05 only exists on sm_100a/sm_103a targets.
#if defined(__CUDA_ARCH_FEAT_SM103_ALL) || defined(__CUDA_ARCH_FEAT_SM100_ALL)
#define HAS_TCGEN05 1
#else
#define HAS_TCGEN05 0
#endif

// ---------------- scratch (device globals: no allocation) -------------------
__device__ __nv_bfloat16 g_xhi[NTOK * DIM];
__device__ __nv_bfloat16 g_xlo[NTOK * DIM];
__device__ __nv_bfloat16 g_whi[NEXP * DIM * DIM];   // transposed: [e][n][k]
__device__ __nv_bfloat16 g_wlo[NEXP * DIM * DIM];
__device__ float         g_h  [NTOK * DIM];

// ---------------- PTX helpers (guarded) -------------------------------------
#if HAS_TCGEN05
__device__ __forceinline__ uint32_t smem_u32(const void* p) {
    uint32_t a;
    asm("{ .reg .u64 t; cvta.to.shared.u64 t, %1; cvt.u32.u64 %0, t; }" : "=r"(a) : "l"(p));
    return a;
}
__device__ __forceinline__ uint32_t elect_one_pred() {
    uint32_t p;
    asm volatile("{\n\t.reg .pred p;\n\telect.sync _|p, 0xFFFFFFFF;\n\tselp.b32 %0, 1, 0, p;\n\t}" : "=r"(p));
    return p;
}

#define MBARRIER_INIT(addr, cnt) \
    asm volatile("mbarrier.init.shared.b64 [%0], %1;" :: "r"(addr), "r"(cnt) : "memory")
#define MBARRIER_INVAL(addr) \
    asm volatile("mbarrier.inval.shared.b64 [%0];" :: "r"(addr) : "memory")
#define MBARRIER_EXPECT_TX(addr, bytes) \
    asm volatile("mbarrier.arrive.expect_tx.shared.b64 _, [%0], %1;" :: "r"(addr), "r"(bytes) : "memory")
#define MBARRIER_WAIT_PARITY(addr, par) do {                                        \
    uint32_t _m = (addr), _p = (par), _d;                                           \
    asm volatile("{\n\t.reg .pred p;\n\t"                                           \
        "mbarrier.try_wait.parity.acquire.cta.shared::cta.b64 p, [%1], %2;\n\t"     \
        "selp.b32 %0, 1, 0, p;\n\t}" : "=r"(_d) : "r"(_m), "r"(_p) : "memory");     \
    if (!_d) {                                                                      \
        asm volatile("{\n\t.reg .pred P1;\n\t"                                      \
            "WL_%=:\n\t"                                                            \
            "mbarrier.try_wait.parity.acquire.cta.shared::cta.b64 P1, [%0], %1, 0x989680;\n\t" \
            "@P1 bra.uni WD_%=;\n\tbra.uni WL_%=;\n\tWD_%=:\n\t}"                   \
            :: "r"(_m), "r"(_p) : "memory");                                        \
    } } while (0)

#define TMA_LOAD_2D(smem_addr, map, cx, cy, mbar) \
    asm volatile("cp.async.bulk.tensor.2d.shared::cta.global.tile.mbarrier::complete_tx::bytes " \
        "[%0], [%1, {%2, %3}], [%4];" \
        :: "r"(smem_addr), "l"(map), "r"(cx), "r"(cy), "r"(mbar) : "memory")

#define TCGEN05_ALLOC(smem_addr, ncols) \
    asm volatile("tcgen05.alloc.cta_group::1.sync.aligned.shared::cta.b32 [%0], %1;" \
                 :: "r"(smem_addr), "r"(ncols) : "memory")
#define TCGEN05_DEALLOC(tmem, ncols) \
    asm volatile("tcgen05.dealloc.cta_group::1.sync.aligned.b32 %0, %1;" :: "r"(tmem), "r"(ncols))
#define TCGEN05_RELINQ() \
    asm volatile("tcgen05.relinquish_alloc_permit.cta_group::1.sync.aligned;")
#define TCGEN05_COMMIT(mbar) \
    asm volatile("tcgen05.commit.cta_group::1.mbarrier::arrive::one.shared::cluster.b64 [%0];" \
                 :: "r"(mbar) : "memory")
#define TCGEN05_FENCE_AFTER() \
    asm volatile("tcgen05.fence::after_thread_sync;" ::: "memory")
#define TCGEN05_FENCE_BEFORE() \
    asm volatile("tcgen05.fence::before_thread_sync;" ::: "memory")
#define TCGEN05_WAIT_LD() \
    asm volatile("tcgen05.wait::ld.sync.aligned;" ::: "memory")

#define TCGEN05_LD_X32(r, tmem_addr) \
    asm volatile("tcgen05.ld.sync.aligned.32x32b.x32.b32 " \
        "{%0, %1, %2, %3, %4, %5, %6, %7, %8, %9, %10, %11, %12, %13, %14, %15, " \
        " %16, %17, %18, %19, %20, %21, %22, %23, %24, %25, %26, %27, %28, %29, %30, %31}, [%32];" \
        : "=r"((r)[0]),  "=r"((r)[1]),  "=r"((r)[2]),  "=r"((r)[3]),  \
          "=r"((r)[4]),  "=r"((r)[5]),  "=r"((r)[6]),  "=r"((r)[7]),  \
          "=r"((r)[8]),  "=r"((r)[9]),  "=r"((r)[10]), "=r"((r)[11]), \
          "=r"((r)[12]), "=r"((r)[13]), "=r"((r)[14]), "=r"((r)[15]), \
          "=r"((r)[16]), "=r"((r)[17]), "=r"((r)[18]), "=r"((r)[19]), \
          "=r"((r)[20]), "=r"((r)[21]), "=r"((r)[22]), "=r"((r)[23]), \
          "=r"((r)[24]), "=r"((r)[25]), "=r"((r)[26]), "=r"((r)[27]), \
          "=r"((r)[28]), "=r"((r)[29]), "=r"((r)[30]), "=r"((r)[31]) \
        : "r"(tmem_addr))

// SS-mode bf16 MMA, cta_group::1, fp32 accumulate in TMEM
__device__ __forceinline__ void mma_f16_ss(uint32_t d_tmem, uint64_t a_desc,
                                           uint64_t b_desc, uint32_t idesc, bool acc) {
    uint32_t en = acc ? 1u : 0u, z = 0u;
    asm volatile("{\n\t.reg .pred p;\n\tsetp.ne.u32 p, %5, 0;\n\t"
        "tcgen05.mma.cta_group::1.kind::f16 [%0], %1, %2, %3, {%4, %4, %4, %4}, p;\n\t}"
        :: "r"(d_tmem), "l"(a_desc), "l"(b_desc), "r"(idesc), "r"(z), "r"(en) : "memory");
}

// SW64 K-major descriptor: layout=4 (SW64), version=1, SBO=32 (512B = 8 rows x 64B), LBO=1
static __device__ __forceinline__ uint64_t make_desc_sw64(uint32_t addr) {
    const uint64_t BASE = (4ull << 61) | (1ull << 46) | (32ull << 32) | (1ull << 16);
    return BASE | ((uint64_t)(addr >> 4) & 0x3FFFull);
}

// idesc: F32 out, BF16 in, M=128, N=256
#define MMA_IDESC ((1u << 4) | (1u << 7) | (1u << 10) | ((256u / 8) << 17) | ((128u / 16) << 24))
#endif // HAS_TCGEN05

// ---------------------------------------------------------------------------
// Merged conversion: X fp32 -> (hi,lo) bf16 AND W[e][k][n] -> Wt(hi/lo)[e][n][k]
// blocks [0, 8192): X path. blocks [8192, 16384): W transpose path.
// ---------------------------------------------------------------------------
__global__ __launch_bounds__(256)
void convert_all_kernel(const float* __restrict__ X,
                        __nv_bfloat16* __restrict__ Xhi,
                        __nv_bfloat16* __restrict__ Xlo,
                        const float* __restrict__ W,
                        __nv_bfloat16* __restrict__ Whi,
                        __nv_bfloat16* __restrict__ Wlo)
{
    __shared__ float t[32][33];
    const int bid = blockIdx.x;
    const int tid = threadIdx.x;

    if (bid < 8192) {
        int idx = bid * 256 + tid;                  // float4 index
        float4 v = ((const float4*)X)[idx];
        __nv_bfloat16 h[4], l[4];
        float vv[4] = {v.x, v.y, v.z, v.w};
        #pragma unroll
        for (int i = 0; i < 4; ++i) {
            h[i] = __float2bfloat16(vv[i]);
            l[i] = __float2bfloat16(vv[i] - __bfloat162float(h[i]));
        }
        *(uint2*)(Xhi + (size_t)idx * 4) = *(uint2*)h;
        *(uint2*)(Xlo + (size_t)idx * 4) = *(uint2*)l;
    } else {
        const int b   = bid - 8192;
        const int e   = b >> 10;
        const int rem = b & 1023;
        const int k0  = (rem >> 5) * 32;
        const int n0  = (rem & 31) * 32;
        const int tx  = tid & 31;
        const int ty  = tid >> 5;                   // 0..7

        const float* Wp = W + (size_t)e * DIM * DIM;
        #pragma unroll
        for (int r = 0; r < 4; ++r) {
            int k = k0 + ty + 8 * r;
            t[ty + 8 * r][tx] = Wp[(size_t)k * DIM + n0 + tx];
        }
        __syncthreads();
        #pragma unroll
        for (int r = 0; r < 4; ++r) {
            int n = n0 + ty + 8 * r;
            float v = t[tx][ty + 8 * r];
            __nv_bfloat16 h = __float2bfloat16(v);
            __nv_bfloat16 l = __float2bfloat16(v - __bfloat162float(h));
            size_t off = (size_t)e * DIM * DIM + (size_t)n * DIM + k0 + tx;
            Whi[off] = h;
            Wlo[off] = l;
        }
    }
}

// ---------------------------------------------------------------------------
// GEMM: per expert e, H = relu(X_e @ W_e + b_e), bf16x3 split.
//   sm_103a: tile M=128 N=256 (TMEM 256 cols), 2 stages, TMA producer,
//   128 threads, 2 CTAs/SM — co-resident CTAs hide each other's ring latency.
// ---------------------------------------------------------------------------
#define NSTAGE      2
#define K_CHUNK     32
#define N_CHUNKS    32               // 1024 / 32
#define STAGE_BYTES 49152            // Ahi8K Alo8K Bhi16K Blo16K
#define ST_A_HI 0
#define ST_A_LO 8192
#define ST_B_HI 16384
#define ST_B_LO 32768
#define OFF_BIAS  (NSTAGE * STAGE_BYTES)       // 98304, 1KB
#define OFF_TPTR  (OFF_BIAS + 1024)
#define OFF_FULL  (OFF_TPTR + 16)              // 2 x 8B
#define OFF_EMPTY (OFF_FULL + 16)              // 2 x 8B
#define OFF_FINAL (OFF_EMPTY + 16)
#define SMEM_SIZE (OFF_FINAL + 16)

__global__ __launch_bounds__(128, 2)
void gemm_tc_kernel(const __grid_constant__ CUtensorMap tmXhi,
                    const __grid_constant__ CUtensorMap tmXlo,
                    const __grid_constant__ CUtensorMap tmWhi,
                    const __grid_constant__ CUtensorMap tmWlo,
                    const __nv_bfloat16* __restrict__ Xhi,
                    const __nv_bfloat16* __restrict__ Xlo,
                    const __nv_bfloat16* __restrict__ Whi,
                    const __nv_bfloat16* __restrict__ Wlo,
                    const float* __restrict__ bias,
                    float* __restrict__ H)
{
#if HAS_TCGEN05
    extern __shared__ __align__(1024) char smem[];
    const uint32_t sbase  = smem_u32(smem);
    const int e      = blockIdx.z;
    const int tile_n = blockIdx.x * 256;
    const int tile_m = blockIdx.y * 128;
    const int tid    = threadIdx.x;
    const int wid    = tid >> 5;
    const int lid    = tid & 31;

    if (wid == 0) {
        TCGEN05_ALLOC(sbase + OFF_TPTR, 256);
        TCGEN05_RELINQ();
    }
    if (tid == 0) {
        #pragma unroll
        for (int s = 0; s < NSTAGE; ++s) {
            MBARRIER_INIT(sbase + OFF_FULL  + s * 8, 1);   // expect_tx by tid0
            MBARRIER_INIT(sbase + OFF_EMPTY + s * 8, 1);   // one commit
        }
        MBARRIER_INIT(sbase + OFF_FINAL, 1);
    }
    ((float*)(smem + OFF_BIAS))[tid]       = bias[e * DIM + tile_n + tid];
    ((float*)(smem + OFF_BIAS))[tid + 128] = bias[e * DIM + tile_n + tid + 128];
    __syncthreads();
    uint32_t tmem;
    asm volatile("ld.shared.b32 %0, [%1];" : "=r"(tmem) : "r"(sbase + OFF_TPTR));

    if (tid == 0) {
        // ------- producer: 4 TMA issues per chunk
        const int rowA = e * CAP + tile_m;           // X rows (128-row box)
        const int rowB = e * DIM + tile_n;           // Wt rows (256-row box)
        int st = 0;
        for (int c = 0; c < N_CHUNKS; ++c) {
            if (c >= NSTAGE)
                MBARRIER_WAIT_PARITY(sbase + OFF_EMPTY + st * 8, ((c >> 1) - 1) & 1);
            const uint32_t bb = sbase + st * STAGE_BYTES;
            const uint32_t fb = sbase + OFF_FULL + st * 8;
            const int cx = c * K_CHUNK;
            MBARRIER_EXPECT_TX(fb, STAGE_BYTES);
            TMA_LOAD_2D(bb + ST_A_HI, &tmXhi, cx, rowA, fb);
            TMA_LOAD_2D(bb + ST_A_LO, &tmXlo, cx, rowA, fb);
            TMA_LOAD_2D(bb + ST_B_HI, &tmWhi, cx, rowB, fb);
            TMA_LOAD_2D(bb + ST_B_LO, &tmWlo, cx, rowB, fb);
            st ^= 1;
        }
    } else if (wid == 1) {
        // ---------------- MMA warp (single elected thread)
        if (elect_one_pred()) {
            int st = 0;
            for (int c = 0; c < N_CHUNKS; ++c) {
                MBARRIER_WAIT_PARITY(sbase + OFF_FULL + st * 8, (c >> 1) & 1);
                const uint32_t bb = sbase + st * STAGE_BYTES;
                uint64_t dAh = make_desc_sw64(bb + ST_A_HI);
                uint64_t dAl = make_desc_sw64(bb + ST_A_LO);
                uint64_t dBh = make_desc_sw64(bb + ST_B_HI);
                uint64_t dBl = make_desc_sw64(bb + ST_B_LO);
                #pragma unroll
                for (int kk = 0; kk < 2; ++kk) {     // K=16 steps (+2 units = 32B)
                    mma_f16_ss(tmem, dAh + kk * 2, dBh + kk * 2, MMA_IDESC,
                               !(c == 0 && kk == 0));
                    mma_f16_ss(tmem, dAh + kk * 2, dBl + kk * 2, MMA_IDESC, true);
                    mma_f16_ss(tmem, dAl + kk * 2, dBh + kk * 2, MMA_IDESC, true);
                }
                TCGEN05_COMMIT(sbase + OFF_EMPTY + st * 8);
                st ^= 1;
            }
            TCGEN05_COMMIT(sbase + OFF_FINAL);
        }
    }

    // ---------------- epilogue: 4 warps (32 M-rows each) after final commit
    MBARRIER_WAIT_PARITY(sbase + OFF_FINAL, 0);
    TCGEN05_FENCE_AFTER();

    {
        const int row = tile_m + wid * 32 + lid;
        float* outp = H + (size_t)(e * CAP + row) * DIM + tile_n;
        const float* bs = (const float*)(smem + OFF_BIAS);
        #pragma unroll
        for (int base = 0; base < 256; base += 32) {
            uint32_t r[32];
            TCGEN05_LD_X32(r, tmem + base);
            TCGEN05_WAIT_LD();
            float v[32];
            #pragma unroll
            for (int i = 0; i < 32; ++i)
                v[i] = fmaxf(__uint_as_float(r[i]) + bs[base + i], 0.f);
            #pragma unroll
            for (int q = 0; q < 8; ++q)
                *(float4*)(outp + base + q * 4) = *(float4*)&v[q * 4];
        }
        TCGEN05_FENCE_BEFORE();
    }
    __syncthreads();
    if (tid == 0) {
        #pragma unroll
        for (int s = 0; s < NSTAGE; ++s) {
            MBARRIER_INVAL(sbase + OFF_FULL  + s * 8);
            MBARRIER_INVAL(sbase + OFF_EMPTY + s * 8);
        }
        MBARRIER_INVAL(sbase + OFF_FINAL);
    }
    __syncthreads();
    if (wid == 0) TCGEN05_DEALLOC(tmem, 256);

#else
    // ---------------- trivial correct fallback (family-level image; not used on GB300)
    const int e      = blockIdx.z;
    const int tile_n = blockIdx.x * 256;
    const int tile_m = blockIdx.y * 128;
    const int tid    = threadIdx.x;
    const int row    = tile_m + tid;
    const __nv_bfloat16* Ahp = Xhi + (size_t)(e * CAP + row) * DIM;
    const __nv_bfloat16* Alp = Xlo + (size_t)(e * CAP + row) * DIM;
    for (int n = 0; n < 256; ++n) {
        const __nv_bfloat16* Bhp = Whi + ((size_t)e * DIM + tile_n + n) * DIM;
        const __nv_bfloat16* Blp = Wlo + ((size_t)e * DIM + tile_n + n) * DIM;
        float s = 0.f;
        for (int k = 0; k < DIM; ++k) {
            float a = __bfloat162float(Ahp[k]) + __bfloat162float(Alp[k]);
            float b = __bfloat162float(Bhp[k]) + __bfloat162float(Blp[k]);
            s = fmaf(a, b, s);
        }
        s += bias[e * DIM + tile_n + n];
        H[(size_t)(e * CAP + row) * DIM + tile_n + n] = fmaxf(s, 0.f);
    }
#endif
}

// ---------------------------------------------------------------------------
// LayerNorm over D=1024 per row; one 256-thread CTA per token. (R3 version)
// ---------------------------------------------------------------------------
__global__ __launch_bounds__(256)
void layernorm_kernel(const float* __restrict__ H,
                      const float* __restrict__ gamma,
                      const float* __restrict__ beta,
                      float* __restrict__ out)
{
    const int row = blockIdx.x;
    const int e   = row >> 10;
    const int tid = threadIdx.x;

    const float* h = H + (size_t)row * DIM;
    float4 v = *(const float4*)(h + tid * 4);

    float s  = v.x + v.y + v.z + v.w;
    float sq = v.x * v.x + v.y * v.y + v.z * v.z + v.w * v.w;

    #pragma unroll
    for (int off = 16; off > 0; off >>= 1) {
        s  += __shfl_xor_sync(0xffffffffu, s,  off);
        sq += __shfl_xor_sync(0xffffffffu, sq, off);
    }

    __shared__ float red_s[8], red_q[8];
    const int wid = tid >> 5, lid = tid & 31;
    if (lid == 0) { red_s[wid] = s; red_q[wid] = sq; }
    __syncthreads();

    __shared__ float s_mean, s_rstd;
    if (wid == 0) {
        float ts = (lid < 8) ? red_s[lid] : 0.f;
        float tq = (lid < 8) ? red_q[lid] : 0.f;
        #pragma unroll
        for (int off = 4; off > 0; off >>= 1) {
            ts += __shfl_xor_sync(0xffffffffu, ts, off);
            tq += __shfl_xor_sync(0xffffffffu, tq, off);
        }
        if (lid == 0) {
            float mean = ts * (1.f / DIM);
            float var  = tq * (1.f / DIM) - mean * mean;
            s_mean = mean;
            s_rstd = rsqrtf(var + LN_EPS);
        }
    }
    __syncthreads();

    const float mean = s_mean, rstd = s_rstd;
    float4 g  = *(const float4*)(gamma + (size_t)e * DIM + tid * 4);
    float4 bt = *(const float4*)(beta  + (size_t)e * DIM + tid * 4);

    float4 o;
    o.x = (v.x - mean) * rstd * g.x + bt.x;
    o.y = (v.y - mean) * rstd * g.y + bt.y;
    o.z = (v.z - mean) * rstd * g.z + bt.z;
    o.w = (v.w - mean) * rstd * g.w + bt.w;
    *(float4*)(out + (size_t)row * DIM + tid * 4) = o;
}

// ---------------------------------------------------------------------------
typedef CUresult (CUDAAPI *pfn_encode_t)(
    CUtensorMap*, CUtensorMapDataType, cuuint32_t, void*,
    const cuuint64_t*, const cuuint64_t*, const cuuint32_t*, const cuuint32_t*,
    CUtensorMapInterleave, CUtensorMapSwizzle, CUtensorMapL2promotion,
    CUtensorMapFloatOOBfill);

static void encode_map_2d(pfn_encode_t fn, CUtensorMap* tm, void* ptr, int nrows,
                          unsigned box_rows)
{
    cuuint64_t dims[2]    = {(cuuint64_t)DIM, (cuuint64_t)nrows};
    cuuint64_t strides[1] = {(cuuint64_t)(DIM * 2)};   // bytes per row (bf16)
    cuuint32_t box[2]     = {32, box_rows};            // 64B x box_rows, SW64
    cuuint32_t estr[2]    = {1, 1};
    fn(tm, CU_TENSOR_MAP_DATA_TYPE_BFLOAT16, 2, ptr, dims, strides, box, estr,
       CU_TENSOR_MAP_INTERLEAVE_NONE, CU_TENSOR_MAP_SWIZZLE_64B,
       CU_TENSOR_MAP_L2_PROMOTION_L2_128B, CU_TENSOR_MAP_FLOAT_OOB_FILL_NONE);
}

extern "C" void kernel_launch(void* const* d_in, const int* in_sizes, int n_in,
                              void* d_out, int out_size)
{
    const float* x     = (const float*)d_in[0];
    // d_in[1] = expert_frequency (equal capacities) — unused
    const float* W     = (const float*)d_in[2];
    const float* bias  = (const float*)d_in[3];
    const float* gamma = (const float*)d_in[4];
    const float* beta  = (const float*)d_in[5];
    float*       out   = (float*)d_out;

    __nv_bfloat16 *xhi, *xlo, *whi, *wlo;
    float* h;
    cudaGetSymbolAddress((void**)&xhi, g_xhi);
    cudaGetSymbolAddress((void**)&xlo, g_xlo);
    cudaGetSymbolAddress((void**)&whi, g_whi);
    cudaGetSymbolAddress((void**)&wlo, g_wlo);
    cudaGetSymbolAddress((void**)&h,   g_h);

    static bool init_done = false;
    static CUtensorMap tmXhi, tmXlo, tmWhi, tmWlo;
    if (!init_done) {
        cudaFuncSetAttribute(gemm_tc_kernel,
                             cudaFuncAttributeMaxDynamicSharedMemorySize, SMEM_SIZE);
        void* p = nullptr;
        cudaDriverEntryPointQueryResult qr;
        if (cudaGetDriverEntryPointByVersion("cuTensorMapEncodeTiled", &p, 12000,
                                             cudaEnableDefault, &qr) != cudaSuccess || !p) {
            cudaGetDriverEntryPoint("cuTensorMapEncodeTiled", &p, cudaEnableDefault, &qr);
        }
        pfn_encode_t fn = (pfn_encode_t)p;
        encode_map_2d(fn, &tmXhi, xhi, NTOK, 128);
        encode_map_2d(fn, &tmXlo, xlo, NTOK, 128);
        encode_map_2d(fn, &tmWhi, whi, NEXP * DIM, 256);
        encode_map_2d(fn, &tmWlo, wlo, NEXP * DIM, 256);
        init_done = true;
    }

    convert_all_kernel<<<16384, 256>>>(x, xhi, xlo, W, whi, wlo);

    dim3 grid(DIM / 256, CAP / 128, NEXP);  // 4 x 8 x 8 = 256 CTAs, 2/SM
    gemm_tc_kernel<<<grid, 128, SMEM_SIZE>>>(tmXhi, tmXlo, tmWhi, tmWlo,
                                             xhi, xlo, whi, wlo, bias, h);

    layernorm_kernel<<<NTOK, 256>>>(h, gamma, beta, out);
}

// round 10
// speedup vs baseline: 1.3190x; 1.2875x over previous
#include <cuda_runtime.h>
#include <cuda.h>
#include <cuda_bf16.h>
#include <cstdint>

#define NTOK   8192
#define DIM    1024
#define NEXP   8
#define CAP    1024
#define LN_EPS 1e-5f

// Arch-specific feature gate: tcgen05 only exists on sm_100a/sm_103a targets.
#if defined(__CUDA_ARCH_FEAT_SM103_ALL) || defined(__CUDA_ARCH_FEAT_SM100_ALL)
#define HAS_TCGEN05 1
#else
#define HAS_TCGEN05 0
#endif

// ---------------- scratch (device globals: no allocation) -------------------
__device__ float g_wt[NEXP * DIM * DIM];   // W transposed: [e][n][k], fp32
__device__ float g_h [NTOK * DIM];

// ---------------- PTX helpers (guarded) -------------------------------------
#if HAS_TCGEN05
__device__ __forceinline__ uint32_t smem_u32(const void* p) {
    uint32_t a;
    asm("{ .reg .u64 t; cvta.to.shared.u64 t, %1; cvt.u32.u64 %0, t; }" : "=r"(a) : "l"(p));
    return a;
}
__device__ __forceinline__ uint32_t elect_one_pred() {
    uint32_t p;
    asm volatile("{\n\t.reg .pred p;\n\telect.sync _|p, 0xFFFFFFFF;\n\tselp.b32 %0, 1, 0, p;\n\t}" : "=r"(p));
    return p;
}

#define MBARRIER_INIT(addr, cnt) \
    asm volatile("mbarrier.init.shared.b64 [%0], %1;" :: "r"(addr), "r"(cnt) : "memory")
#define MBARRIER_INVAL(addr) \
    asm volatile("mbarrier.inval.shared.b64 [%0];" :: "r"(addr) : "memory")
#define MBARRIER_EXPECT_TX(addr, bytes) \
    asm volatile("mbarrier.arrive.expect_tx.shared.b64 _, [%0], %1;" :: "r"(addr), "r"(bytes) : "memory")
#define MBARRIER_WAIT_PARITY(addr, par) do {                                        \
    uint32_t _m = (addr), _p = (par), _d;                                           \
    asm volatile("{\n\t.reg .pred p;\n\t"                                           \
        "mbarrier.try_wait.parity.acquire.cta.shared::cta.b64 p, [%1], %2;\n\t"     \
        "selp.b32 %0, 1, 0, p;\n\t}" : "=r"(_d) : "r"(_m), "r"(_p) : "memory");     \
    if (!_d) {                                                                      \
        asm volatile("{\n\t.reg .pred P1;\n\t"                                      \
            "WL_%=:\n\t"                                                            \
            "mbarrier.try_wait.parity.acquire.cta.shared::cta.b64 P1, [%0], %1, 0x989680;\n\t" \
            "@P1 bra.uni WD_%=;\n\tbra.uni WL_%=;\n\tWD_%=:\n\t}"                   \
            :: "r"(_m), "r"(_p) : "memory");                                        \
    } } while (0)

#define TMA_LOAD_2D(smem_addr, map, cx, cy, mbar) \
    asm volatile("cp.async.bulk.tensor.2d.shared::cta.global.tile.mbarrier::complete_tx::bytes " \
        "[%0], [%1, {%2, %3}], [%4];" \
        :: "r"(smem_addr), "l"(map), "r"(cx), "r"(cy), "r"(mbar) : "memory")

#define TCGEN05_ALLOC(smem_addr, ncols) \
    asm volatile("tcgen05.alloc.cta_group::1.sync.aligned.shared::cta.b32 [%0], %1;" \
                 :: "r"(smem_addr), "r"(ncols) : "memory")
#define TCGEN05_DEALLOC(tmem, ncols) \
    asm volatile("tcgen05.dealloc.cta_group::1.sync.aligned.b32 %0, %1;" :: "r"(tmem), "r"(ncols))
#define TCGEN05_RELINQ() \
    asm volatile("tcgen05.relinquish_alloc_permit.cta_group::1.sync.aligned;")
#define TCGEN05_COMMIT(mbar) \
    asm volatile("tcgen05.commit.cta_group::1.mbarrier::arrive::one.shared::cluster.b64 [%0];" \
                 :: "r"(mbar) : "memory")
#define TCGEN05_FENCE_AFTER() \
    asm volatile("tcgen05.fence::after_thread_sync;" ::: "memory")
#define TCGEN05_FENCE_BEFORE() \
    asm volatile("tcgen05.fence::before_thread_sync;" ::: "memory")
#define TCGEN05_WAIT_LD() \
    asm volatile("tcgen05.wait::ld.sync.aligned;" ::: "memory")

#define TCGEN05_LD_X32(r, tmem_addr) \
    asm volatile("tcgen05.ld.sync.aligned.32x32b.x32.b32 " \
        "{%0, %1, %2, %3, %4, %5, %6, %7, %8, %9, %10, %11, %12, %13, %14, %15, " \
        " %16, %17, %18, %19, %20, %21, %22, %23, %24, %25, %26, %27, %28, %29, %30, %31}, [%32];" \
        : "=r"((r)[0]),  "=r"((r)[1]),  "=r"((r)[2]),  "=r"((r)[3]),  \
          "=r"((r)[4]),  "=r"((r)[5]),  "=r"((r)[6]),  "=r"((r)[7]),  \
          "=r"((r)[8]),  "=r"((r)[9]),  "=r"((r)[10]), "=r"((r)[11]), \
          "=r"((r)[12]), "=r"((r)[13]), "=r"((r)[14]), "=r"((r)[15]), \
          "=r"((r)[16]), "=r"((r)[17]), "=r"((r)[18]), "=r"((r)[19]), \
          "=r"((r)[20]), "=r"((r)[21]), "=r"((r)[22]), "=r"((r)[23]), \
          "=r"((r)[24]), "=r"((r)[25]), "=r"((r)[26]), "=r"((r)[27]), \
          "=r"((r)[28]), "=r"((r)[29]), "=r"((r)[30]), "=r"((r)[31]) \
        : "r"(tmem_addr))

// SS-mode tf32 MMA, cta_group::1, fp32 accumulate in TMEM (K=8 per step)
__device__ __forceinline__ void mma_tf32_ss(uint32_t d_tmem, uint64_t a_desc,
                                            uint64_t b_desc, uint32_t idesc, bool acc) {
    uint32_t en = acc ? 1u : 0u, z = 0u;
    asm volatile("{\n\t.reg .pred p;\n\tsetp.ne.u32 p, %5, 0;\n\t"
        "tcgen05.mma.cta_group::1.kind::tf32 [%0], %1, %2, %3, {%4, %4, %4, %4}, p;\n\t}"
        :: "r"(d_tmem), "l"(a_desc), "l"(b_desc), "r"(idesc), "r"(z), "r"(en) : "memory");
}

// SW128 K-major descriptor (LBO=1, SBO=64, version=1, layout=SW128) — proven in R3.
// Rows here are 32 f32 = 128 B = one SW128 atom row, same geometry as R3's 64 bf16.
static __device__ __forceinline__ uint64_t make_desc_sw128(uint32_t addr) {
    const uint64_t BASE = (2ull << 61) | (1ull << 46) | (64ull << 32) | (1ull << 16);
    return BASE | ((uint64_t)(addr >> 4) & 0x3FFFull);
}

// idesc: dtype F32 (1<<4), atype TF32 (2<<7), btype TF32 (2<<10), N=256, M=128
#define MMA_IDESC ((1u << 4) | (2u << 7) | (2u << 10) | ((256u / 8) << 17) | ((128u / 16) << 24))
#endif // HAS_TCGEN05

// ---------------------------------------------------------------------------
// W transpose (fp32): W[e][k][n] -> Wt[e][n][k], coalesced reads AND writes.
// 32x32 tiles, 256 threads; writes are float4 (16B) per thread.
// ---------------------------------------------------------------------------
__global__ __launch_bounds__(256)
void transpose_w_kernel(const float* __restrict__ W, float* __restrict__ Wt)
{
    __shared__ float t[32][33];
    const int e  = blockIdx.z;
    const int k0 = blockIdx.y * 32;
    const int n0 = blockIdx.x * 32;
    const int tid = threadIdx.x;
    const int tx = tid & 31;
    const int ty = tid >> 5;            // 0..7

    const float* Wp = W + (size_t)e * DIM * DIM;
    #pragma unroll
    for (int r = 0; r < 4; ++r)
        t[ty + 8 * r][tx] = Wp[(size_t)(k0 + ty + 8 * r) * DIM + n0 + tx];
    __syncthreads();

    // write: 32 output rows (n), 8 threads x float4 per row
    const int rn = tid >> 3;            // 0..31 output row within tile
    const int c4 = tid & 7;             // 0..7 float4 group
    float4 v;
    v.x = t[c4 * 4 + 0][rn];
    v.y = t[c4 * 4 + 1][rn];
    v.z = t[c4 * 4 + 2][rn];
    v.w = t[c4 * 4 + 3][rn];
    *(float4*)(Wt + (size_t)e * DIM * DIM + (size_t)(n0 + rn) * DIM + k0 + c4 * 4) = v;
}

// ---------------------------------------------------------------------------
// GEMM: per expert e, H = relu(X_e @ W_e + b_e), single-pass tf32.
//   Tile M=256 (2 MMA halves) x N=256, K_CHUNK=32, NSTAGE=3, TMA producer,
//   128 CTAs = 1 wave. rel_err budget: tf32 rounding ~4e-4 << 1e-3.
// ---------------------------------------------------------------------------
#define NSTAGE      3
#define K_CHUNK     32
#define N_CHUNKS    32               // 1024 / 32
#define STAGE_BYTES 65536            // A 32K (256r x 128B) + B 32K (256r x 128B)
#define ST_A 0
#define ST_B 32768
#define OFF_BIAS  (NSTAGE * STAGE_BYTES)       // 196608, 1KB
#define OFF_TPTR  (OFF_BIAS + 1024)
#define OFF_FULL  (OFF_TPTR + 16)              // 3 x 8B
#define OFF_EMPTY (OFF_FULL + 24)              // 3 x 8B
#define OFF_FINAL (OFF_EMPTY + 24)
#define SMEM_SIZE (OFF_FINAL + 16)

__global__ __launch_bounds__(256, 1)
void gemm_tc_kernel(const __grid_constant__ CUtensorMap tmX,
                    const __grid_constant__ CUtensorMap tmW,
                    const float* __restrict__ X,
                    const float* __restrict__ Wt,
                    const float* __restrict__ bias,
                    float* __restrict__ H)
{
#if HAS_TCGEN05
    extern __shared__ __align__(1024) char smem[];
    const uint32_t sbase  = smem_u32(smem);
    const int e      = blockIdx.z;
    const int tile_n = blockIdx.x * 256;
    const int tile_m = blockIdx.y * 256;
    const int tid    = threadIdx.x;
    const int wid    = tid >> 5;
    const int lid    = tid & 31;

    if (wid == 0) {
        TCGEN05_ALLOC(sbase + OFF_TPTR, 512);
        TCGEN05_RELINQ();
    }
    if (tid == 0) {
        #pragma unroll
        for (int s = 0; s < NSTAGE; ++s) {
            MBARRIER_INIT(sbase + OFF_FULL  + s * 8, 1);   // expect_tx by tid0
            MBARRIER_INIT(sbase + OFF_EMPTY + s * 8, 1);   // one commit
        }
        MBARRIER_INIT(sbase + OFF_FINAL, 1);
    }
    ((float*)(smem + OFF_BIAS))[tid] = bias[e * DIM + tile_n + tid];
    __syncthreads();
    uint32_t tmem;
    asm volatile("ld.shared.b32 %0, [%1];" : "=r"(tmem) : "r"(sbase + OFF_TPTR));

    if (tid == 0) {
        // ------- producer: 2 TMA issues per chunk (A 256 rows, B 256 rows)
        const int rowA = e * CAP + tile_m;
        const int rowB = e * DIM + tile_n;
        int st = 0, it = 0;
        for (int c = 0; c < N_CHUNKS; ++c) {
            if (c >= NSTAGE)
                MBARRIER_WAIT_PARITY(sbase + OFF_EMPTY + st * 8, (it - 1) & 1);
            const uint32_t bb = sbase + st * STAGE_BYTES;
            const uint32_t fb = sbase + OFF_FULL + st * 8;
            const int cx = c * K_CHUNK;
            MBARRIER_EXPECT_TX(fb, STAGE_BYTES);
            TMA_LOAD_2D(bb + ST_A, &tmX, cx, rowA, fb);
            TMA_LOAD_2D(bb + ST_B, &tmW, cx, rowB, fb);
            if (++st == NSTAGE) { st = 0; ++it; }
        }
    } else if (wid == 1) {
        // ---------------- MMA warp (single elected thread)
        if (elect_one_pred()) {
            int st = 0, it = 0;
            for (int c = 0; c < N_CHUNKS; ++c) {
                MBARRIER_WAIT_PARITY(sbase + OFF_FULL + st * 8, it & 1);
                const uint32_t bb = sbase + st * STAGE_BYTES;
                uint64_t dA = make_desc_sw128(bb + ST_A);
                uint64_t dB = make_desc_sw128(bb + ST_B);
                #pragma unroll
                for (int h = 0; h < 2; ++h) {                 // M halves
                    const uint32_t D   = tmem + h * 256;
                    const uint64_t hof = h * 1024;            // 128 rows x 128B = 1024 units
                    #pragma unroll
                    for (int kk = 0; kk < 4; ++kk) {          // K=8 steps (+2 units = 32B)
                        mma_tf32_ss(D, dA + hof + kk * 2, dB + kk * 2, MMA_IDESC,
                                    !(c == 0 && kk == 0));
                    }
                }
                TCGEN05_COMMIT(sbase + OFF_EMPTY + st * 8);
                if (++st == NSTAGE) { st = 0; ++it; }
            }
            TCGEN05_COMMIT(sbase + OFF_FINAL);
        }
    }

    // ---------------- epilogue: 8 warps (half = wid>>2, sub = wid&3)
    MBARRIER_WAIT_PARITY(sbase + OFF_FINAL, 0);
    TCGEN05_FENCE_AFTER();

    {
        const int half = wid >> 2, sub = wid & 3;
        const int row  = tile_m + half * 128 + sub * 32 + lid;
        float* outp = H + (size_t)(e * CAP + row) * DIM + tile_n;
        const float* bs = (const float*)(smem + OFF_BIAS);
        const uint32_t dbase = tmem + half * 256;
        #pragma unroll
        for (int base = 0; base < 256; base += 32) {
            uint32_t r[32];
            TCGEN05_LD_X32(r, dbase + base);
            TCGEN05_WAIT_LD();
            float v[32];
            #pragma unroll
            for (int i = 0; i < 32; ++i)
                v[i] = fmaxf(__uint_as_float(r[i]) + bs[base + i], 0.f);
            #pragma unroll
            for (int q = 0; q < 8; ++q)
                *(float4*)(outp + base + q * 4) = *(float4*)&v[q * 4];
        }
        TCGEN05_FENCE_BEFORE();
    }
    __syncthreads();
    if (tid == 0) {
        #pragma unroll
        for (int s = 0; s < NSTAGE; ++s) {
            MBARRIER_INVAL(sbase + OFF_FULL  + s * 8);
            MBARRIER_INVAL(sbase + OFF_EMPTY + s * 8);
        }
        MBARRIER_INVAL(sbase + OFF_FINAL);
    }
    __syncthreads();
    if (wid == 0) TCGEN05_DEALLOC(tmem, 512);

#else
    // ---------------- trivial correct fallback (family-level image; not used on GB300)
    const int e      = blockIdx.z;
    const int tile_n = blockIdx.x * 256;
    const int tile_m = blockIdx.y * 256;
    const int tid    = threadIdx.x;
    const int row    = tile_m + tid;
    const float* Ap = X + (size_t)(e * CAP + row) * DIM;
    for (int n = 0; n < 256; ++n) {
        const float* Bp = Wt + ((size_t)e * DIM + tile_n + n) * DIM;
        float s = 0.f;
        for (int k = 0; k < DIM; ++k) s = fmaf(Ap[k], Bp[k], s);
        s += bias[e * DIM + tile_n + n];
        H[(size_t)(e * CAP + row) * DIM + tile_n + n] = fmaxf(s, 0.f);
    }
#endif
}

// ---------------------------------------------------------------------------
// LayerNorm over D=1024 per row; one 256-thread CTA per token. (R3 version)
// ---------------------------------------------------------------------------
__global__ __launch_bounds__(256)
void layernorm_kernel(const float* __restrict__ H,
                      const float* __restrict__ gamma,
                      const float* __restrict__ beta,
                      float* __restrict__ out)
{
    const int row = blockIdx.x;
    const int e   = row >> 10;
    const int tid = threadIdx.x;

    const float* h = H + (size_t)row * DIM;
    float4 v = *(const float4*)(h + tid * 4);

    float s  = v.x + v.y + v.z + v.w;
    float sq = v.x * v.x + v.y * v.y + v.z * v.z + v.w * v.w;

    #pragma unroll
    for (int off = 16; off > 0; off >>= 1) {
        s  += __shfl_xor_sync(0xffffffffu, s,  off);
        sq += __shfl_xor_sync(0xffffffffu, sq, off);
    }

    __shared__ float red_s[8], red_q[8];
    const int wid = tid >> 5, lid = tid & 31;
    if (lid == 0) { red_s[wid] = s; red_q[wid] = sq; }
    __syncthreads();

    __shared__ float s_mean, s_rstd;
    if (wid == 0) {
        float ts = (lid < 8) ? red_s[lid] : 0.f;
        float tq = (lid < 8) ? red_q[lid] : 0.f;
        #pragma unroll
        for (int off = 4; off > 0; off >>= 1) {
            ts += __shfl_xor_sync(0xffffffffu, ts, off);
            tq += __shfl_xor_sync(0xffffffffu, tq, off);
        }
        if (lid == 0) {
            float mean = ts * (1.f / DIM);
            float var  = tq * (1.f / DIM) - mean * mean;
            s_mean = mean;
            s_rstd = rsqrtf(var + LN_EPS);
        }
    }
    __syncthreads();

    const float mean = s_mean, rstd = s_rstd;
    float4 g  = *(const float4*)(gamma + (size_t)e * DIM + tid * 4);
    float4 bt = *(const float4*)(beta  + (size_t)e * DIM + tid * 4);

    float4 o;
    o.x = (v.x - mean) * rstd * g.x + bt.x;
    o.y = (v.y - mean) * rstd * g.y + bt.y;
    o.z = (v.z - mean) * rstd * g.z + bt.z;
    o.w = (v.w - mean) * rstd * g.w + bt.w;
    *(float4*)(out + (size_t)row * DIM + tid * 4) = o;
}

// ---------------------------------------------------------------------------
typedef CUresult (CUDAAPI *pfn_encode_t)(
    CUtensorMap*, CUtensorMapDataType, cuuint32_t, void*,
    const cuuint64_t*, const cuuint64_t*, const cuuint32_t*, const cuuint32_t*,
    CUtensorMapInterleave, CUtensorMapSwizzle, CUtensorMapL2promotion,
    CUtensorMapFloatOOBfill);

static void encode_map_f32(pfn_encode_t fn, CUtensorMap* tm, void* ptr, int nrows)
{
    cuuint64_t dims[2]    = {(cuuint64_t)DIM, (cuuint64_t)nrows};
    cuuint64_t strides[1] = {(cuuint64_t)(DIM * 4)};   // bytes per row (f32)
    cuuint32_t box[2]     = {32, 256};                 // 128B x 256 rows, SW128
    cuuint32_t estr[2]    = {1, 1};
    fn(tm, CU_TENSOR_MAP_DATA_TYPE_FLOAT32, 2, ptr, dims, strides, box, estr,
       CU_TENSOR_MAP_INTERLEAVE_NONE, CU_TENSOR_MAP_SWIZZLE_128B,
       CU_TENSOR_MAP_L2_PROMOTION_L2_128B, CU_TENSOR_MAP_FLOAT_OOB_FILL_NONE);
}

extern "C" void kernel_launch(void* const* d_in, const int* in_sizes, int n_in,
                              void* d_out, int out_size)
{
    const float* x     = (const float*)d_in[0];
    // d_in[1] = expert_frequency (equal capacities) — unused
    const float* W     = (const float*)d_in[2];
    const float* bias  = (const float*)d_in[3];
    const float* gamma = (const float*)d_in[4];
    const float* beta  = (const float*)d_in[5];
    float*       out   = (float*)d_out;

    float *wt, *h;
    cudaGetSymbolAddress((void**)&wt, g_wt);
    cudaGetSymbolAddress((void**)&h,  g_h);

    static bool init_done = false;
    static CUtensorMap tmX, tmW;
    static const float* x_cached = nullptr;
    if (!init_done || x_cached != x) {
        cudaFuncSetAttribute(gemm_tc_kernel,
                             cudaFuncAttributeMaxDynamicSharedMemorySize, SMEM_SIZE);
        void* p = nullptr;
        cudaDriverEntryPointQueryResult qr;
        if (cudaGetDriverEntryPointByVersion("cuTensorMapEncodeTiled", &p, 12000,
                                             cudaEnableDefault, &qr) != cudaSuccess || !p) {
            cudaGetDriverEntryPoint("cuTensorMapEncodeTiled", &p, cudaEnableDefault, &qr);
        }
        pfn_encode_t fn = (pfn_encode_t)p;
        encode_map_f32(fn, &tmX, (void*)x, NTOK);
        encode_map_f32(fn, &tmW, wt, NEXP * DIM);
        init_done = true;
        x_cached = x;
    }

    transpose_w_kernel<<<dim3(32, 32, NEXP), 256>>>(W, wt);

    dim3 grid(DIM / 256, CAP / 256, NEXP);  // 4 x 4 x 8 = 128 CTAs, 1 wave
    gemm_tc_kernel<<<grid, 256, SMEM_SIZE>>>(tmX, tmW, x, wt, bias, h);

    layernorm_kernel<<<NTOK, 256>>>(h, gamma, beta, out);
}

// round 11
// speedup vs baseline: 1.3704x; 1.0390x over previous
#include <cuda_runtime.h>
#include <cuda.h>
#include <cuda_bf16.h>
#include <cstdint>

#define NTOK   8192
#define DIM    1024
#define NEXP   8
#define CAP    1024
#define LN_EPS 1e-5f

// Arch-specific feature gate: tcgen05 only exists on sm_100a/sm_103a targets.
#if defined(__CUDA_ARCH_FEAT_SM103_ALL) || defined(__CUDA_ARCH_FEAT_SM100_ALL)
#define HAS_TCGEN05 1
#else
#define HAS_TCGEN05 0
#endif

// ---------------- scratch (device globals: no allocation) -------------------
__device__ float g_wt[NEXP * DIM * DIM];   // W transposed: [e][n][k], fp32
__device__ float g_h [NTOK * DIM];

// ---------------- PTX helpers (guarded) -------------------------------------
#if HAS_TCGEN05
__device__ __forceinline__ uint32_t smem_u32(const void* p) {
    uint32_t a;
    asm("{ .reg .u64 t; cvta.to.shared.u64 t, %1; cvt.u32.u64 %0, t; }" : "=r"(a) : "l"(p));
    return a;
}
__device__ __forceinline__ uint32_t elect_one_pred() {
    uint32_t p;
    asm volatile("{\n\t.reg .pred p;\n\telect.sync _|p, 0xFFFFFFFF;\n\tselp.b32 %0, 1, 0, p;\n\t}" : "=r"(p));
    return p;
}

#define MBARRIER_INIT(addr, cnt) \
    asm volatile("mbarrier.init.shared.b64 [%0], %1;" :: "r"(addr), "r"(cnt) : "memory")
#define MBARRIER_INVAL(addr) \
    asm volatile("mbarrier.inval.shared.b64 [%0];" :: "r"(addr) : "memory")
#define MBARRIER_EXPECT_TX(addr, bytes) \
    asm volatile("mbarrier.arrive.expect_tx.shared.b64 _, [%0], %1;" :: "r"(addr), "r"(bytes) : "memory")
#define MBARRIER_WAIT_PARITY(addr, par) do {                                        \
    uint32_t _m = (addr), _p = (par), _d;                                           \
    asm volatile("{\n\t.reg .pred p;\n\t"                                           \
        "mbarrier.try_wait.parity.acquire.cta.shared::cta.b64 p, [%1], %2;\n\t"     \
        "selp.b32 %0, 1, 0, p;\n\t}" : "=r"(_d) : "r"(_m), "r"(_p) : "memory");     \
    if (!_d) {                                                                      \
        asm volatile("{\n\t.reg .pred P1;\n\t"                                      \
            "WL_%=:\n\t"                                                            \
            "mbarrier.try_wait.parity.acquire.cta.shared::cta.b64 P1, [%0], %1, 0x989680;\n\t" \
            "@P1 bra.uni WD_%=;\n\tbra.uni WL_%=;\n\tWD_%=:\n\t}"                   \
            :: "r"(_m), "r"(_p) : "memory");                                        \
    } } while (0)

#define TMA_LOAD_2D(smem_addr, map, cx, cy, mbar) \
    asm volatile("cp.async.bulk.tensor.2d.shared::cta.global.tile.mbarrier::complete_tx::bytes " \
        "[%0], [%1, {%2, %3}], [%4];" \
        :: "r"(smem_addr), "l"(map), "r"(cx), "r"(cy), "r"(mbar) : "memory")

#define TCGEN05_ALLOC(smem_addr, ncols) \
    asm volatile("tcgen05.alloc.cta_group::1.sync.aligned.shared::cta.b32 [%0], %1;" \
                 :: "r"(smem_addr), "r"(ncols) : "memory")
#define TCGEN05_DEALLOC(tmem, ncols) \
    asm volatile("tcgen05.dealloc.cta_group::1.sync.aligned.b32 %0, %1;" :: "r"(tmem), "r"(ncols))
#define TCGEN05_RELINQ() \
    asm volatile("tcgen05.relinquish_alloc_permit.cta_group::1.sync.aligned;")
#define TCGEN05_COMMIT(mbar) \
    asm volatile("tcgen05.commit.cta_group::1.mbarrier::arrive::one.shared::cluster.b64 [%0];" \
                 :: "r"(mbar) : "memory")
#define TCGEN05_FENCE_AFTER() \
    asm volatile("tcgen05.fence::after_thread_sync;" ::: "memory")
#define TCGEN05_FENCE_BEFORE() \
    asm volatile("tcgen05.fence::before_thread_sync;" ::: "memory")
#define TCGEN05_WAIT_LD() \
    asm volatile("tcgen05.wait::ld.sync.aligned;" ::: "memory")

#define TCGEN05_LD_X32(r, tmem_addr) \
    asm volatile("tcgen05.ld.sync.aligned.32x32b.x32.b32 " \
        "{%0, %1, %2, %3, %4, %5, %6, %7, %8, %9, %10, %11, %12, %13, %14, %15, " \
        " %16, %17, %18, %19, %20, %21, %22, %23, %24, %25, %26, %27, %28, %29, %30, %31}, [%32];" \
        : "=r"((r)[0]),  "=r"((r)[1]),  "=r"((r)[2]),  "=r"((r)[3]),  \
          "=r"((r)[4]),  "=r"((r)[5]),  "=r"((r)[6]),  "=r"((r)[7]),  \
          "=r"((r)[8]),  "=r"((r)[9]),  "=r"((r)[10]), "=r"((r)[11]), \
          "=r"((r)[12]), "=r"((r)[13]), "=r"((r)[14]), "=r"((r)[15]), \
          "=r"((r)[16]), "=r"((r)[17]), "=r"((r)[18]), "=r"((r)[19]), \
          "=r"((r)[20]), "=r"((r)[21]), "=r"((r)[22]), "=r"((r)[23]), \
          "=r"((r)[24]), "=r"((r)[25]), "=r"((r)[26]), "=r"((r)[27]), \
          "=r"((r)[28]), "=r"((r)[29]), "=r"((r)[30]), "=r"((r)[31]) \
        : "r"(tmem_addr))

// SS-mode tf32 MMA, cta_group::1, fp32 accumulate in TMEM (K=8 per step)
__device__ __forceinline__ void mma_tf32_ss(uint32_t d_tmem, uint64_t a_desc,
                                            uint64_t b_desc, uint32_t idesc, bool acc) {
    uint32_t en = acc ? 1u : 0u, z = 0u;
    asm volatile("{\n\t.reg .pred p;\n\tsetp.ne.u32 p, %5, 0;\n\t"
        "tcgen05.mma.cta_group::1.kind::tf32 [%0], %1, %2, %3, {%4, %4, %4, %4}, p;\n\t}"
        :: "r"(d_tmem), "l"(a_desc), "l"(b_desc), "r"(idesc), "r"(z), "r"(en) : "memory");
}

// SW64 K-major descriptor (layout=4, version=1, SBO=32 = 512B per 8-row group,
// LBO=1) — byte-geometry proven in R6/R7 with 64B rows; dtype-agnostic.
static __device__ __forceinline__ uint64_t make_desc_sw64(uint32_t addr) {
    const uint64_t BASE = (4ull << 61) | (1ull << 46) | (32ull << 32) | (1ull << 16);
    return BASE | ((uint64_t)(addr >> 4) & 0x3FFFull);
}

// idesc: dtype F32 (1<<4), atype TF32 (2<<7), btype TF32 (2<<10), N=256, M=128
#define MMA_IDESC ((1u << 4) | (2u << 7) | (2u << 10) | ((256u / 8) << 17) | ((128u / 16) << 24))
#endif // HAS_TCGEN05

// ---------------------------------------------------------------------------
// W transpose (fp32): 64x64 tile per CTA, float4 reads AND writes.
// 2048 CTAs total. 2-way LDS conflicts on the gather — negligible vs DRAM.
// ---------------------------------------------------------------------------
__global__ __launch_bounds__(256)
void transpose_w_kernel(const float* __restrict__ W, float* __restrict__ Wt)
{
    __shared__ float t[64][65];
    const int e  = blockIdx.z;
    const int k0 = blockIdx.y * 64;
    const int n0 = blockIdx.x * 64;
    const int tid = threadIdx.x;
    const int rr  = tid >> 4;           // 0..15
    const int c4  = tid & 15;           // 0..15 float4 group

    const float* Wp = W + (size_t)e * DIM * DIM;
    #pragma unroll
    for (int i = 0; i < 4; ++i) {
        int row = rr + i * 16;
        float4 v = *(const float4*)(Wp + (size_t)(k0 + row) * DIM + n0 + c4 * 4);
        t[row][c4 * 4 + 0] = v.x;
        t[row][c4 * 4 + 1] = v.y;
        t[row][c4 * 4 + 2] = v.z;
        t[row][c4 * 4 + 3] = v.w;
    }
    __syncthreads();

    float* Wtp = Wt + (size_t)e * DIM * DIM;
    #pragma unroll
    for (int i = 0; i < 4; ++i) {
        int n = rr + i * 16;
        float4 v;
        v.x = t[c4 * 4 + 0][n];
        v.y = t[c4 * 4 + 1][n];
        v.z = t[c4 * 4 + 2][n];
        v.w = t[c4 * 4 + 3][n];
        *(float4*)(Wtp + (size_t)(n0 + n) * DIM + k0 + c4 * 4) = v;
    }
}

// ---------------------------------------------------------------------------
// GEMM: per expert e, H = relu(X_e @ W_e + b_e), single-pass tf32.
//   Tile M=256 (2 MMA halves) x N=256, K_CHUNK=16 (64B rows, SW64),
//   NSTAGE=6 deep pipeline, TMA producer, 128 CTAs = 1 wave.
// ---------------------------------------------------------------------------
#define NSTAGE      6
#define K_CHUNK     16
#define N_CHUNKS    64               // 1024 / 16
#define STAGE_BYTES 32768            // A 16K (256r x 64B) + B 16K (256r x 64B)
#define ST_A 0
#define ST_B 16384
#define OFF_BIAS  (NSTAGE * STAGE_BYTES)       // 196608, 1KB
#define OFF_TPTR  (OFF_BIAS + 1024)
#define OFF_FULL  (OFF_TPTR + 16)              // 6 x 8B
#define OFF_EMPTY (OFF_FULL + 48)              // 6 x 8B
#define OFF_FINAL (OFF_EMPTY + 48)
#define SMEM_SIZE (OFF_FINAL + 16)

__global__ __launch_bounds__(256, 1)
void gemm_tc_kernel(const __grid_constant__ CUtensorMap tmX,
                    const __grid_constant__ CUtensorMap tmW,
                    const float* __restrict__ X,
                    const float* __restrict__ Wt,
                    const float* __restrict__ bias,
                    float* __restrict__ H)
{
#if HAS_TCGEN05
    extern __shared__ __align__(1024) char smem[];
    const uint32_t sbase  = smem_u32(smem);
    const int e      = blockIdx.z;
    const int tile_n = blockIdx.x * 256;
    const int tile_m = blockIdx.y * 256;
    const int tid    = threadIdx.x;
    const int wid    = tid >> 5;
    const int lid    = tid & 31;

    if (wid == 0) {
        TCGEN05_ALLOC(sbase + OFF_TPTR, 512);
        TCGEN05_RELINQ();
    }
    if (tid == 0) {
        #pragma unroll
        for (int s = 0; s < NSTAGE; ++s) {
            MBARRIER_INIT(sbase + OFF_FULL  + s * 8, 1);   // expect_tx by tid0
            MBARRIER_INIT(sbase + OFF_EMPTY + s * 8, 1);   // one commit
        }
        MBARRIER_INIT(sbase + OFF_FINAL, 1);
    }
    ((float*)(smem + OFF_BIAS))[tid] = bias[e * DIM + tile_n + tid];
    __syncthreads();
    uint32_t tmem;
    asm volatile("ld.shared.b32 %0, [%1];" : "=r"(tmem) : "r"(sbase + OFF_TPTR));

    if (tid == 0) {
        // ------- producer: 2 TMA issues per chunk (A 256 rows, B 256 rows)
        const int rowA = e * CAP + tile_m;
        const int rowB = e * DIM + tile_n;
        int st = 0, it = 0;
        for (int c = 0; c < N_CHUNKS; ++c) {
            if (c >= NSTAGE)
                MBARRIER_WAIT_PARITY(sbase + OFF_EMPTY + st * 8, (it - 1) & 1);
            const uint32_t bb = sbase + st * STAGE_BYTES;
            const uint32_t fb = sbase + OFF_FULL + st * 8;
            const int cx = c * K_CHUNK;
            MBARRIER_EXPECT_TX(fb, STAGE_BYTES);
            TMA_LOAD_2D(bb + ST_A, &tmX, cx, rowA, fb);
            TMA_LOAD_2D(bb + ST_B, &tmW, cx, rowB, fb);
            if (++st == NSTAGE) { st = 0; ++it; }
        }
    } else if (wid == 1) {
        // ---------------- MMA warp (single elected thread)
        if (elect_one_pred()) {
            int st = 0, it = 0;
            for (int c = 0; c < N_CHUNKS; ++c) {
                MBARRIER_WAIT_PARITY(sbase + OFF_FULL + st * 8, it & 1);
                const uint32_t bb = sbase + st * STAGE_BYTES;
                uint64_t dA = make_desc_sw64(bb + ST_A);
                uint64_t dB = make_desc_sw64(bb + ST_B);
                #pragma unroll
                for (int h = 0; h < 2; ++h) {                 // M halves
                    const uint32_t D   = tmem + h * 256;
                    const uint64_t hof = h * 512;             // 128 rows x 64B = 512 units
                    #pragma unroll
                    for (int kk = 0; kk < 2; ++kk) {          // K=8 steps (+2 units = 32B)
                        mma_tf32_ss(D, dA + hof + kk * 2, dB + kk * 2, MMA_IDESC,
                                    !(c == 0 && kk == 0));
                    }
                }
                TCGEN05_COMMIT(sbase + OFF_EMPTY + st * 8);
                if (++st == NSTAGE) { st = 0; ++it; }
            }
            TCGEN05_COMMIT(sbase + OFF_FINAL);
        }
    }

    // ---------------- epilogue: 8 warps (half = wid>>2, sub = wid&3)
    MBARRIER_WAIT_PARITY(sbase + OFF_FINAL, 0);
    TCGEN05_FENCE_AFTER();

    {
        const int half = wid >> 2, sub = wid & 3;
        const int row  = tile_m + half * 128 + sub * 32 + lid;
        float* outp = H + (size_t)(e * CAP + row) * DIM + tile_n;
        const float* bs = (const float*)(smem + OFF_BIAS);
        const uint32_t dbase = tmem + half * 256;
        #pragma unroll
        for (int base = 0; base < 256; base += 32) {
            uint32_t r[32];
            TCGEN05_LD_X32(r, dbase + base);
            TCGEN05_WAIT_LD();
            float v[32];
            #pragma unroll
            for (int i = 0; i < 32; ++i)
                v[i] = fmaxf(__uint_as_float(r[i]) + bs[base + i], 0.f);
            #pragma unroll
            for (int q = 0; q < 8; ++q)
                *(float4*)(outp + base + q * 4) = *(float4*)&v[q * 4];
        }
        TCGEN05_FENCE_BEFORE();
    }
    __syncthreads();
    if (tid == 0) {
        #pragma unroll
        for (int s = 0; s < NSTAGE; ++s) {
            MBARRIER_INVAL(sbase + OFF_FULL  + s * 8);
            MBARRIER_INVAL(sbase + OFF_EMPTY + s * 8);
        }
        MBARRIER_INVAL(sbase + OFF_FINAL);
    }
    __syncthreads();
    if (wid == 0) TCGEN05_DEALLOC(tmem, 512);

#else
    // ---------------- trivial correct fallback (family-level image; not used on GB300)
    const int e      = blockIdx.z;
    const int tile_n = blockIdx.x * 256;
    const int tile_m = blockIdx.y * 256;
    const int tid    = threadIdx.x;
    const int row    = tile_m + tid;
    const float* Ap = X + (size_t)(e * CAP + row) * DIM;
    for (int n = 0; n < 256; ++n) {
        const float* Bp = Wt + ((size_t)e * DIM + tile_n + n) * DIM;
        float s = 0.f;
        for (int k = 0; k < DIM; ++k) s = fmaf(Ap[k], Bp[k], s);
        s += bias[e * DIM + tile_n + n];
        H[(size_t)(e * CAP + row) * DIM + tile_n + n] = fmaxf(s, 0.f);
    }
#endif
}

// ---------------------------------------------------------------------------
// LayerNorm: 2 rows per 512-thread CTA (256 threads per row, R3 row shape).
// ---------------------------------------------------------------------------
__global__ __launch_bounds__(512)
void layernorm_kernel(const float* __restrict__ H,
                      const float* __restrict__ gamma,
                      const float* __restrict__ beta,
                      float* __restrict__ out)
{
    const int tid  = threadIdx.x;
    const int r    = tid >> 8;               // 0..1 row within CTA
    const int rt   = tid & 255;              // thread within row
    const int row  = blockIdx.x * 2 + r;
    const int e    = row >> 10;

    const float* h = H + (size_t)row * DIM;
    float4 v = *(const float4*)(h + rt * 4);

    float s  = v.x + v.y + v.z + v.w;
    float sq = v.x * v.x + v.y * v.y + v.z * v.z + v.w * v.w;

    #pragma unroll
    for (int off = 16; off > 0; off >>= 1) {
        s  += __shfl_xor_sync(0xffffffffu, s,  off);
        sq += __shfl_xor_sync(0xffffffffu, sq, off);
    }

    __shared__ float red_s[16], red_q[16];
    const int wid = tid >> 5, lid = tid & 31;
    if (lid == 0) { red_s[wid] = s; red_q[wid] = sq; }
    __syncthreads();

    float ts = 0.f, tq = 0.f;
    #pragma unroll
    for (int w = 0; w < 8; ++w) {
        ts += red_s[r * 8 + w];
        tq += red_q[r * 8 + w];
    }
    const float mean = ts * (1.f / DIM);
    const float var  = tq * (1.f / DIM) - mean * mean;
    const float rstd = rsqrtf(var + LN_EPS);

    float4 g  = *(const float4*)(gamma + (size_t)e * DIM + rt * 4);
    float4 bt = *(const float4*)(beta  + (size_t)e * DIM + rt * 4);

    float4 o;
    o.x = (v.x - mean) * rstd * g.x + bt.x;
    o.y = (v.y - mean) * rstd * g.y + bt.y;
    o.z = (v.z - mean) * rstd * g.z + bt.z;
    o.w = (v.w - mean) * rstd * g.w + bt.w;
    *(float4*)(out + (size_t)row * DIM + rt * 4) = o;
}

// ---------------------------------------------------------------------------
typedef CUresult (CUDAAPI *pfn_encode_t)(
    CUtensorMap*, CUtensorMapDataType, cuuint32_t, void*,
    const cuuint64_t*, const cuuint64_t*, const cuuint32_t*, const cuuint32_t*,
    CUtensorMapInterleave, CUtensorMapSwizzle, CUtensorMapL2promotion,
    CUtensorMapFloatOOBfill);

static void encode_map_f32(pfn_encode_t fn, CUtensorMap* tm, void* ptr, int nrows)
{
    cuuint64_t dims[2]    = {(cuuint64_t)DIM, (cuuint64_t)nrows};
    cuuint64_t strides[1] = {(cuuint64_t)(DIM * 4)};   // bytes per row (f32)
    cuuint32_t box[2]     = {16, 256};                 // 64B x 256 rows, SW64
    cuuint32_t estr[2]    = {1, 1};
    fn(tm, CU_TENSOR_MAP_DATA_TYPE_FLOAT32, 2, ptr, dims, strides, box, estr,
       CU_TENSOR_MAP_INTERLEAVE_NONE, CU_TENSOR_MAP_SWIZZLE_64B,
       CU_TENSOR_MAP_L2_PROMOTION_L2_128B, CU_TENSOR_MAP_FLOAT_OOB_FILL_NONE);
}

extern "C" void kernel_launch(void* const* d_in, const int* in_sizes, int n_in,
                              void* d_out, int out_size)
{
    const float* x     = (const float*)d_in[0];
    // d_in[1] = expert_frequency (equal capacities) — unused
    const float* W     = (const float*)d_in[2];
    const float* bias  = (const float*)d_in[3];
    const float* gamma = (const float*)d_in[4];
    const float* beta  = (const float*)d_in[5];
    float*       out   = (float*)d_out;

    float *wt, *h;
    cudaGetSymbolAddress((void**)&wt, g_wt);
    cudaGetSymbolAddress((void**)&h,  g_h);

    static bool init_done = false;
    static CUtensorMap tmX, tmW;
    static const float* x_cached = nullptr;
    if (!init_done || x_cached != x) {
        cudaFuncSetAttribute(gemm_tc_kernel,
                             cudaFuncAttributeMaxDynamicSharedMemorySize, SMEM_SIZE);
        void* p = nullptr;
        cudaDriverEntryPointQueryResult qr;
        if (cudaGetDriverEntryPointByVersion("cuTensorMapEncodeTiled", &p, 12000,
                                             cudaEnableDefault, &qr) != cudaSuccess || !p) {
            cudaGetDriverEntryPoint("cuTensorMapEncodeTiled", &p, cudaEnableDefault, &qr);
        }
        pfn_encode_t fn = (pfn_encode_t)p;
        encode_map_f32(fn, &tmX, (void*)x, NTOK);
        encode_map_f32(fn, &tmW, wt, NEXP * DIM);
        init_done = true;
        x_cached = x;
    }

    transpose_w_kernel<<<dim3(16, 16, NEXP), 256>>>(W, wt);

    dim3 grid(DIM / 256, CAP / 256, NEXP);  // 4 x 4 x 8 = 128 CTAs, 1 wave
    gemm_tc_kernel<<<grid, 256, SMEM_SIZE>>>(tmX, tmW, x, wt, bias, h);

    layernorm_kernel<<<NTOK / 2, 512>>>(h, gamma, beta, out);
}